// round 1
// baseline (speedup 1.0000x reference)
#include <cuda_runtime.h>
#include <cuda_fp16.h>
#include <mma.h>

using namespace nvcuda;

#define BSZ  4
#define CCH  256
#define NTOK 4096

// ---------------- static device scratch (no allocation allowed) ----------------
__device__ __half g_th_hi[(size_t)BSZ * NTOK * CCH];
__device__ __half g_th_lo[(size_t)BSZ * NTOK * CCH];
__device__ __half g_ph_hi[(size_t)BSZ * NTOK * CCH];
__device__ __half g_ph_lo[(size_t)BSZ * NTOK * CCH];
__device__ __half g_gv  [(size_t)BSZ * NTOK * CCH];
__device__ float  g_S   [(size_t)BSZ * NTOK * NTOK];   // 256 MB
__device__ __half g_P   [(size_t)BSZ * NTOK * NTOK];   // 128 MB
__device__ float  g_Y   [(size_t)BSZ * NTOK * CCH];    // 16 MB

// =============================================================================
// Kernel 1: projections  theta/phi/g[b,n,oc] = sum_c w[oc,c] * x[b,c,n]  (fp32)
// grid (N/64, C/64, B*3), block 256. theta/phi written as hi+lo fp16 split.
// =============================================================================
__global__ void proj_kernel(const float* __restrict__ x,
                            const float* __restrict__ w_th,
                            const float* __restrict__ w_ph,
                            const float* __restrict__ w_g) {
    const int b = blockIdx.z / 3;
    const int w = blockIdx.z % 3;
    const float* __restrict__ wp = (w == 0) ? w_th : (w == 1) ? w_ph : w_g;
    const int n0 = blockIdx.x * 64;
    const int o0 = blockIdx.y * 64;

    __shared__ float As[16][64];   // [k][n]
    __shared__ float Ws[16][64];   // [k][oc]

    const int t  = threadIdx.x;
    const int tx = t & 15;         // oc micro
    const int ty = t >> 4;         // n micro

    float acc[4][4] = {};
    const float* __restrict__ xb = x + (size_t)b * CCH * NTOK;

    for (int k0 = 0; k0 < CCH; k0 += 16) {
        __syncthreads();
        {   // A tile: 16 k-rows x 64 n
            const int kk = t >> 4, nn = (t & 15) * 4;
            *(float4*)&As[kk][nn] =
                *(const float4*)&xb[(size_t)(k0 + kk) * NTOK + n0 + nn];
        }
        {   // W tile (transposed load): 64 oc rows x 4 k each
            const int oo = t & 63, kk4 = (t >> 6) * 4;
            float4 v = *(const float4*)&wp[(size_t)(o0 + oo) * CCH + k0 + kk4];
            Ws[kk4 + 0][oo] = v.x; Ws[kk4 + 1][oo] = v.y;
            Ws[kk4 + 2][oo] = v.z; Ws[kk4 + 3][oo] = v.w;
        }
        __syncthreads();
        #pragma unroll
        for (int kk = 0; kk < 16; kk++) {
            float4 a  = *(float4*)&As[kk][ty * 4];
            float4 bv = *(float4*)&Ws[kk][tx * 4];
            float av[4] = {a.x, a.y, a.z, a.w};
            float bw[4] = {bv.x, bv.y, bv.z, bv.w};
            #pragma unroll
            for (int i = 0; i < 4; i++)
                #pragma unroll
                for (int j = 0; j < 4; j++)
                    acc[i][j] += av[i] * bw[j];
        }
    }

    const size_t base = (size_t)b * NTOK * CCH;
    #pragma unroll
    for (int i = 0; i < 4; i++) {
        const int n = n0 + ty * 4 + i;
        #pragma unroll
        for (int j = 0; j < 4; j++) {
            const int oc = o0 + tx * 4 + j;
            const size_t idx = base + (size_t)n * CCH + oc;
            const float v = acc[i][j];
            if (w == 2) {
                g_gv[idx] = __float2half(v);
            } else {
                __half hi = __float2half(v);
                __half lo = __float2half(v - __half2float(hi));
                if (w == 0) { g_th_hi[idx] = hi; g_th_lo[idx] = lo; }
                else        { g_ph_hi[idx] = hi; g_ph_lo[idx] = lo; }
            }
        }
    }
}

// =============================================================================
// Kernel 2: S[b,n,m] = sum_c theta[n,c]*phi[m,c]   split-fp16 wmma (3 MMA/step)
// grid (N/128, N/128, B), block 256 (8 warps: 4 row-groups x 2 col-groups)
// =============================================================================
__global__ void qk_kernel() {
    const int b  = blockIdx.z;
    const int n0 = blockIdx.x * 128;
    const int m0 = blockIdx.y * 128;

    __shared__ __half sAhi[128 * 24];
    __shared__ __half sAlo[128 * 24];
    __shared__ __half sBhi[128 * 24];
    __shared__ __half sBlo[128 * 24];

    const int t    = threadIdx.x;
    const int warp = t >> 5;
    const int wr   = warp & 3;    // 32-row group
    const int wc   = warp >> 2;   // 64-col group

    wmma::fragment<wmma::accumulator, 16, 16, 16, float> acc[2][4];
    #pragma unroll
    for (int i = 0; i < 2; i++)
        #pragma unroll
        for (int j = 0; j < 4; j++)
            wmma::fill_fragment(acc[i][j], 0.0f);

    const __half* __restrict__ Ahi = g_th_hi + (size_t)b * NTOK * CCH;
    const __half* __restrict__ Alo = g_th_lo + (size_t)b * NTOK * CCH;
    const __half* __restrict__ Bhi = g_ph_hi + (size_t)b * NTOK * CCH;
    const __half* __restrict__ Blo = g_ph_lo + (size_t)b * NTOK * CCH;

    const int lrow = t >> 1;
    const int lseg = (t & 1) * 8;

    for (int k0 = 0; k0 < CCH; k0 += 16) {
        __syncthreads();
        *(float4*)&sAhi[lrow * 24 + lseg] =
            *(const float4*)&Ahi[(size_t)(n0 + lrow) * CCH + k0 + lseg];
        *(float4*)&sAlo[lrow * 24 + lseg] =
            *(const float4*)&Alo[(size_t)(n0 + lrow) * CCH + k0 + lseg];
        *(float4*)&sBhi[lrow * 24 + lseg] =
            *(const float4*)&Bhi[(size_t)(m0 + lrow) * CCH + k0 + lseg];
        *(float4*)&sBlo[lrow * 24 + lseg] =
            *(const float4*)&Blo[(size_t)(m0 + lrow) * CCH + k0 + lseg];
        __syncthreads();

        wmma::fragment<wmma::matrix_a, 16, 16, 16, __half, wmma::row_major> ah[2], al[2];
        #pragma unroll
        for (int i = 0; i < 2; i++) {
            wmma::load_matrix_sync(ah[i], &sAhi[(wr * 32 + i * 16) * 24], 24);
            wmma::load_matrix_sync(al[i], &sAlo[(wr * 32 + i * 16) * 24], 24);
        }
        #pragma unroll
        for (int j = 0; j < 4; j++) {
            wmma::fragment<wmma::matrix_b, 16, 16, 16, __half, wmma::col_major> bh, bl;
            wmma::load_matrix_sync(bh, &sBhi[(wc * 64 + j * 16) * 24], 24);
            wmma::load_matrix_sync(bl, &sBlo[(wc * 64 + j * 16) * 24], 24);
            #pragma unroll
            for (int i = 0; i < 2; i++) {
                wmma::mma_sync(acc[i][j], ah[i], bh, acc[i][j]);
                wmma::mma_sync(acc[i][j], ah[i], bl, acc[i][j]);
                wmma::mma_sync(acc[i][j], al[i], bh, acc[i][j]);
            }
        }
    }

    float* __restrict__ Sb = g_S + (size_t)b * NTOK * NTOK;
    #pragma unroll
    for (int i = 0; i < 2; i++)
        #pragma unroll
        for (int j = 0; j < 4; j++) {
            const int n = n0 + wr * 32 + i * 16;
            const int m = m0 + wc * 64 + j * 16;
            wmma::store_matrix_sync(&Sb[(size_t)n * NTOK + m], acc[i][j],
                                    NTOK, wmma::mem_row_major);
        }
}

// =============================================================================
// Kernel 3: row softmax over 4096, fp32 in -> fp16 P out.  grid (N, B) x 256
// =============================================================================
__global__ void softmax_kernel() {
    const int n = blockIdx.x, b = blockIdx.y;
    const float*  __restrict__ row  = g_S + ((size_t)b * NTOK + n) * NTOK;
    __half*       __restrict__ prow = g_P + ((size_t)b * NTOK + n) * NTOK;
    const int t = threadIdx.x;

    float4 v[4];
    float mx = -1e30f;
    #pragma unroll
    for (int c = 0; c < 4; c++) {
        v[c] = ((const float4*)row)[c * 256 + t];
        mx = fmaxf(mx, fmaxf(fmaxf(v[c].x, v[c].y), fmaxf(v[c].z, v[c].w)));
    }

    __shared__ float red[32];
    #pragma unroll
    for (int o = 16; o > 0; o >>= 1) mx = fmaxf(mx, __shfl_xor_sync(0xffffffffu, mx, o));
    if ((t & 31) == 0) red[t >> 5] = mx;
    __syncthreads();
    if (t == 0) {
        float m = red[0];
        #pragma unroll
        for (int i = 1; i < 8; i++) m = fmaxf(m, red[i]);
        red[0] = m;
    }
    __syncthreads();
    mx = red[0];
    __syncthreads();

    float sum = 0.0f;
    #pragma unroll
    for (int c = 0; c < 4; c++) {
        v[c].x = __expf(v[c].x - mx);
        v[c].y = __expf(v[c].y - mx);
        v[c].z = __expf(v[c].z - mx);
        v[c].w = __expf(v[c].w - mx);
        sum += (v[c].x + v[c].y) + (v[c].z + v[c].w);
    }
    #pragma unroll
    for (int o = 16; o > 0; o >>= 1) sum += __shfl_xor_sync(0xffffffffu, sum, o);
    if ((t & 31) == 0) red[t >> 5] = sum;
    __syncthreads();
    if (t == 0) {
        float s = red[0];
        #pragma unroll
        for (int i = 1; i < 8; i++) s += red[i];
        red[0] = s;
    }
    __syncthreads();
    const float inv = 1.0f / red[0];

    #pragma unroll
    for (int c = 0; c < 4; c++) {
        __half2 h01 = __floats2half2_rn(v[c].x * inv, v[c].y * inv);
        __half2 h23 = __floats2half2_rn(v[c].z * inv, v[c].w * inv);
        ((__half2*)prow)[(c * 256 + t) * 2 + 0] = h01;
        ((__half2*)prow)[(c * 256 + t) * 2 + 1] = h23;
    }
}

// =============================================================================
// Kernel 4: Y[b,n,c] = sum_m P[n,m] * g[m,c]    fp16 wmma, K = 4096 (BK=32)
// grid (N/128, C/128, B), block 256 (8 warps: 4 x 2)
// =============================================================================
__global__ void pv_kernel() {
    const int b  = blockIdx.z;
    const int n0 = blockIdx.x * 128;
    const int c0 = blockIdx.y * 128;

    __shared__ __half sA[128 * 40];   // [n][k], ld 40
    __shared__ __half sB[32 * 136];   // [k][c], ld 136

    const __half* __restrict__ P = g_P  + (size_t)b * NTOK * NTOK;
    const __half* __restrict__ G = g_gv + (size_t)b * NTOK * CCH;

    const int t = threadIdx.x;
    const int warp = t >> 5;
    const int wr = warp & 3, wc = warp >> 2;

    wmma::fragment<wmma::accumulator, 16, 16, 16, float> acc[2][4];
    #pragma unroll
    for (int i = 0; i < 2; i++)
        #pragma unroll
        for (int j = 0; j < 4; j++)
            wmma::fill_fragment(acc[i][j], 0.0f);

    const int ar = t >> 1, aoff = (t & 1) * 16;
    const int br = t >> 3, boff = (t & 7) * 16;

    for (int k0 = 0; k0 < NTOK; k0 += 32) {
        __syncthreads();
        {
            const __half* ap = &P[(size_t)(n0 + ar) * NTOK + k0 + aoff];
            *(float4*)&sA[ar * 40 + aoff + 0] = *(const float4*)(ap + 0);
            *(float4*)&sA[ar * 40 + aoff + 8] = *(const float4*)(ap + 8);
        }
        {
            const __half* bp = &G[(size_t)(k0 + br) * CCH + c0 + boff];
            *(float4*)&sB[br * 136 + boff + 0] = *(const float4*)(bp + 0);
            *(float4*)&sB[br * 136 + boff + 8] = *(const float4*)(bp + 8);
        }
        __syncthreads();

        #pragma unroll
        for (int ks = 0; ks < 32; ks += 16) {
            wmma::fragment<wmma::matrix_a, 16, 16, 16, __half, wmma::row_major> a[2];
            #pragma unroll
            for (int i = 0; i < 2; i++)
                wmma::load_matrix_sync(a[i], &sA[(wr * 32 + i * 16) * 40 + ks], 40);
            #pragma unroll
            for (int j = 0; j < 4; j++) {
                wmma::fragment<wmma::matrix_b, 16, 16, 16, __half, wmma::row_major> bf;
                wmma::load_matrix_sync(bf, &sB[ks * 136 + wc * 64 + j * 16], 136);
                #pragma unroll
                for (int i = 0; i < 2; i++)
                    wmma::mma_sync(acc[i][j], a[i], bf, acc[i][j]);
            }
        }
    }

    float* __restrict__ Yb = g_Y + (size_t)b * NTOK * CCH;
    #pragma unroll
    for (int i = 0; i < 2; i++)
        #pragma unroll
        for (int j = 0; j < 4; j++) {
            const int n = n0 + wr * 32 + i * 16;
            const int c = c0 + wc * 64 + j * 16;
            wmma::store_matrix_sync(&Yb[(size_t)n * CCH + c], acc[i][j],
                                    CCH, wmma::mem_row_major);
        }
}

// =============================================================================
// Kernel 5: out[b,c,n] = x[b,c,n] + gamma * sum_c' w_out[c,c'] * Y[b,n,c']
// grid (N/64, C/64, B), block 256   (fp32)
// =============================================================================
__global__ void out_kernel(const float* __restrict__ x,
                           const float* __restrict__ w_out,
                           const float* __restrict__ gamma,
                           float* __restrict__ out) {
    const int b  = blockIdx.z;
    const int n0 = blockIdx.x * 64;
    const int c0 = blockIdx.y * 64;

    __shared__ float As[16][64];   // [k][c]
    __shared__ float Bs[16][64];   // [k][n]

    const int t = threadIdx.x;
    const int tx = t & 15;   // n micro
    const int ty = t >> 4;   // c micro

    float acc[4][4] = {};
    const float* __restrict__ Yb = g_Y + (size_t)b * NTOK * CCH;

    for (int k0 = 0; k0 < CCH; k0 += 16) {
        __syncthreads();
        {
            const int cc = t & 63, kk4 = (t >> 6) * 4;
            float4 v = *(const float4*)&w_out[(size_t)(c0 + cc) * CCH + k0 + kk4];
            As[kk4 + 0][cc] = v.x; As[kk4 + 1][cc] = v.y;
            As[kk4 + 2][cc] = v.z; As[kk4 + 3][cc] = v.w;
        }
        {
            const int nn = t & 63, kk4 = (t >> 6) * 4;
            float4 v = *(const float4*)&Yb[(size_t)(n0 + nn) * CCH + k0 + kk4];
            Bs[kk4 + 0][nn] = v.x; Bs[kk4 + 1][nn] = v.y;
            Bs[kk4 + 2][nn] = v.z; Bs[kk4 + 3][nn] = v.w;
        }
        __syncthreads();
        #pragma unroll
        for (int kk = 0; kk < 16; kk++) {
            float4 a  = *(float4*)&As[kk][ty * 4];
            float4 bv = *(float4*)&Bs[kk][tx * 4];
            float av[4] = {a.x, a.y, a.z, a.w};
            float bw[4] = {bv.x, bv.y, bv.z, bv.w};
            #pragma unroll
            for (int i = 0; i < 4; i++)
                #pragma unroll
                for (int j = 0; j < 4; j++)
                    acc[i][j] += av[i] * bw[j];
        }
    }

    const float gm = *gamma;
    #pragma unroll
    for (int i = 0; i < 4; i++) {
        const int c = c0 + ty * 4 + i;
        const size_t idx = ((size_t)b * CCH + c) * NTOK + n0 + tx * 4;
        float4 xo = *(const float4*)&x[idx];
        float4 r;
        r.x = xo.x + gm * acc[i][0];
        r.y = xo.y + gm * acc[i][1];
        r.z = xo.z + gm * acc[i][2];
        r.w = xo.w + gm * acc[i][3];
        *(float4*)&out[idx] = r;
    }
}

// =============================================================================
extern "C" void kernel_launch(void* const* d_in, const int* in_sizes, int n_in,
                              void* d_out, int out_size) {
    (void)in_sizes; (void)n_in; (void)out_size;
    const float* x      = (const float*)d_in[0];
    const float* w_th   = (const float*)d_in[1];
    const float* w_ph   = (const float*)d_in[2];
    const float* w_g    = (const float*)d_in[3];
    const float* w_out  = (const float*)d_in[4];
    const float* gamma  = (const float*)d_in[5];
    float* out = (float*)d_out;

    proj_kernel   <<<dim3(NTOK / 64, CCH / 64, BSZ * 3), 256>>>(x, w_th, w_ph, w_g);
    qk_kernel     <<<dim3(NTOK / 128, NTOK / 128, BSZ), 256>>>();
    softmax_kernel<<<dim3(NTOK, BSZ), 256>>>();
    pv_kernel     <<<dim3(NTOK / 128, CCH / 128, BSZ), 256>>>();
    out_kernel    <<<dim3(NTOK / 64, CCH / 64, BSZ), 256>>>(x, w_out, gamma, out);
}

// round 2
// speedup vs baseline: 1.2739x; 1.2739x over previous
#include <cuda_runtime.h>
#include <cuda_fp16.h>
#include <cstdint>

#define BSZ  4
#define CCH  256
#define NTOK 4096

#define BM   128
#define BN   32
#define LDSH 264          // half elems per smem row (256 + 8 pad); 528B = 33*16B

// ---------------- static device scratch (no allocation allowed) ----------------
__device__ __half g_th_hi[(size_t)BSZ * NTOK * CCH];
__device__ __half g_th_lo[(size_t)BSZ * NTOK * CCH];
__device__ __half g_ph_hi[(size_t)BSZ * NTOK * CCH];
__device__ __half g_ph_lo[(size_t)BSZ * NTOK * CCH];
__device__ __half g_gv  [(size_t)BSZ * NTOK * CCH];
__device__ float  g_Y   [(size_t)BSZ * NTOK * CCH];

// ---------------- PTX helpers ----------------
__device__ __forceinline__ uint32_t smem_u32(const void* p) {
    return (uint32_t)__cvta_generic_to_shared(p);
}
__device__ __forceinline__ void cp16(uint32_t s, const void* g) {
    asm volatile("cp.async.cg.shared.global [%0], [%1], 16;\n" :: "r"(s), "l"(g));
}
#define CP_COMMIT() asm volatile("cp.async.commit_group;\n" ::: "memory")
#define CP_WAIT(n)  asm volatile("cp.async.wait_group %0;\n" :: "n"(n) : "memory")

__device__ __forceinline__ void ldsm4(uint32_t& r0, uint32_t& r1, uint32_t& r2, uint32_t& r3,
                                      uint32_t a) {
    asm volatile("ldmatrix.sync.aligned.m8n8.x4.shared.b16 {%0,%1,%2,%3}, [%4];\n"
                 : "=r"(r0), "=r"(r1), "=r"(r2), "=r"(r3) : "r"(a));
}
__device__ __forceinline__ void ldsm4t(uint32_t& r0, uint32_t& r1, uint32_t& r2, uint32_t& r3,
                                       uint32_t a) {
    asm volatile("ldmatrix.sync.aligned.m8n8.x4.trans.shared.b16 {%0,%1,%2,%3}, [%4];\n"
                 : "=r"(r0), "=r"(r1), "=r"(r2), "=r"(r3) : "r"(a));
}
__device__ __forceinline__ void mma16816(float* c, uint32_t a0, uint32_t a1, uint32_t a2,
                                         uint32_t a3, uint32_t b0, uint32_t b1) {
    asm volatile("mma.sync.aligned.m16n8k16.row.col.f32.f16.f16.f32 "
                 "{%0,%1,%2,%3}, {%4,%5,%6,%7}, {%8,%9}, {%0,%1,%2,%3};\n"
                 : "+f"(c[0]), "+f"(c[1]), "+f"(c[2]), "+f"(c[3])
                 : "r"(a0), "r"(a1), "r"(a2), "r"(a3), "r"(b0), "r"(b1));
}
__device__ __forceinline__ uint32_t h2pack(float a, float b) {
    __half2 h = __floats2half2_rn(a, b);
    return *reinterpret_cast<uint32_t*>(&h);
}

// Load a [32 x 256] half tile into smem (ld = LDSH) via cp.async (4 x 16B per thread)
__device__ __forceinline__ void load_tile32(__half* dst, const __half* src, int t) {
    #pragma unroll
    for (int i = 0; i < 4; i++) {
        int l = t + (i << 8);
        int r = l >> 5, c = (l & 31) << 3;
        cp16(smem_u32(dst + r * LDSH + c), src + (r << 8) + c);
    }
}

// =============================================================================
// Kernel 1: projections  theta/phi/g[b,n,oc] = sum_c w[oc,c] * x[b,c,n]  (fp32)
// =============================================================================
__global__ void proj_kernel(const float* __restrict__ x,
                            const float* __restrict__ w_th,
                            const float* __restrict__ w_ph,
                            const float* __restrict__ w_g) {
    const int b = blockIdx.z / 3;
    const int w = blockIdx.z % 3;
    const float* __restrict__ wp = (w == 0) ? w_th : (w == 1) ? w_ph : w_g;
    const int n0 = blockIdx.x * 64;
    const int o0 = blockIdx.y * 64;

    __shared__ float As[16][64];
    __shared__ float Ws[16][64];

    const int t  = threadIdx.x;
    const int tx = t & 15;
    const int ty = t >> 4;

    float acc[4][4] = {};
    const float* __restrict__ xb = x + (size_t)b * CCH * NTOK;

    for (int k0 = 0; k0 < CCH; k0 += 16) {
        __syncthreads();
        {
            const int kk = t >> 4, nn = (t & 15) * 4;
            *(float4*)&As[kk][nn] =
                *(const float4*)&xb[(size_t)(k0 + kk) * NTOK + n0 + nn];
        }
        {
            const int oo = t & 63, kk4 = (t >> 6) * 4;
            float4 v = *(const float4*)&wp[(size_t)(o0 + oo) * CCH + k0 + kk4];
            Ws[kk4 + 0][oo] = v.x; Ws[kk4 + 1][oo] = v.y;
            Ws[kk4 + 2][oo] = v.z; Ws[kk4 + 3][oo] = v.w;
        }
        __syncthreads();
        #pragma unroll
        for (int kk = 0; kk < 16; kk++) {
            float4 a  = *(float4*)&As[kk][ty * 4];
            float4 bv = *(float4*)&Ws[kk][tx * 4];
            float av[4] = {a.x, a.y, a.z, a.w};
            float bw[4] = {bv.x, bv.y, bv.z, bv.w};
            #pragma unroll
            for (int i = 0; i < 4; i++)
                #pragma unroll
                for (int j = 0; j < 4; j++)
                    acc[i][j] += av[i] * bw[j];
        }
    }

    const size_t base = (size_t)b * NTOK * CCH;
    #pragma unroll
    for (int i = 0; i < 4; i++) {
        const int n = n0 + ty * 4 + i;
        #pragma unroll
        for (int j = 0; j < 4; j++) {
            const int oc = o0 + tx * 4 + j;
            const size_t idx = base + (size_t)n * CCH + oc;
            const float v = acc[i][j];
            if (w == 2) {
                g_gv[idx] = __float2half(v);
            } else {
                __half hi = __float2half(v);
                __half lo = __float2half(v - __half2float(hi));
                if (w == 0) { g_th_hi[idx] = hi; g_th_lo[idx] = lo; }
                else        { g_ph_hi[idx] = hi; g_ph_lo[idx] = lo; }
            }
        }
    }
}

// =============================================================================
// Kernel 2: fused flash attention  Y = softmax(theta phi^T) g^T   (per batch)
// grid (NTOK/BM, BSZ), 256 threads (8 warps x 16 query rows each)
// Split-fp16 QK (3 MMA), online softmax in regs, fp16 PV, fp32 O accum.
// =============================================================================
extern __shared__ char smem_raw[];

__global__ void __launch_bounds__(256, 1) flash_kernel() {
    const int b  = blockIdx.y;
    const int n0 = blockIdx.x * BM;

    __half* sQh = (__half*)smem_raw;          // 128 x LDSH
    __half* sQl = sQh + BM * LDSH;
    __half* sKh = sQl + BM * LDSH;            // 32 x LDSH
    __half* sKl = sKh + BN * LDSH;
    __half* sV  = sKl + BN * LDSH;

    const int t    = threadIdx.x;
    const int lane = t & 31;
    const int warp = t >> 5;
    const int wr0  = warp * 16;

    const __half* __restrict__ Qh = g_th_hi + ((size_t)b * NTOK + n0) * CCH;
    const __half* __restrict__ Ql = g_th_lo + ((size_t)b * NTOK + n0) * CCH;
    const __half* __restrict__ Kh = g_ph_hi + (size_t)b * NTOK * CCH;
    const __half* __restrict__ Kl = g_ph_lo + (size_t)b * NTOK * CCH;
    const __half* __restrict__ Vv = g_gv    + (size_t)b * NTOK * CCH;

    // ---- preload Q (resident) and first K/V tiles
    #pragma unroll
    for (int i = 0; i < 16; i++) {
        int l = t + (i << 8);
        int r = l >> 5, c = (l & 31) << 3;
        cp16(smem_u32(sQh + r * LDSH + c), Qh + (r << 8) + c);
        cp16(smem_u32(sQl + r * LDSH + c), Ql + (r << 8) + c);
    }
    load_tile32(sKh, Kh, t);
    load_tile32(sKl, Kl, t);
    load_tile32(sV,  Vv, t);
    CP_COMMIT();
    CP_WAIT(0);
    __syncthreads();

    // ---- ldmatrix per-lane base addresses
    const int gi = lane >> 3, li = lane & 7;
    const uint32_t aH = smem_u32(sQh + (wr0 + (lane & 15)) * LDSH + ((lane >> 4) << 3));
    const uint32_t aL = smem_u32(sQl + (wr0 + (lane & 15)) * LDSH + ((lane >> 4) << 3));
    const int bKey = ((gi >> 1) << 3) + li;       // QK B: rows = keys
    const int bCh  = (gi & 1) << 3;
    const uint32_t bH0 = smem_u32(sKh + bKey * LDSH + bCh);
    const uint32_t bH1 = bH0 + 16 * LDSH * 2;
    const uint32_t bL0 = smem_u32(sKl + bKey * LDSH + bCh);
    const uint32_t bL1 = bL0 + 16 * LDSH * 2;
    const int vKey = ((gi & 1) << 3) + li;        // PV B (trans): rows = keys
    const int vCh  = (gi >> 1) << 3;
    const uint32_t vB0 = smem_u32(sV + vKey * LDSH + vCh);
    const uint32_t vB1 = vB0 + 16 * LDSH * 2;

    // ---- state
    float o[32][4];
    #pragma unroll
    for (int nt = 0; nt < 32; nt++) { o[nt][0] = o[nt][1] = o[nt][2] = o[nt][3] = 0.0f; }
    float m0 = -1e30f, m1 = -1e30f, l0 = 0.0f, l1 = 0.0f;

    for (int it = 0; it < NTOK / BN; it++) {
        // ---- QK: S[16 x 32] per warp, split-fp16 (3 MMAs per tile)
        float sc[4][4];
        #pragma unroll
        for (int j = 0; j < 4; j++) sc[j][0] = sc[j][1] = sc[j][2] = sc[j][3] = 0.0f;

        #pragma unroll 4
        for (int kc = 0; kc < 16; kc++) {
            const uint32_t ko = kc * 32;   // 16 halves * 2B
            uint32_t a0, a1, a2, a3, x0, x1, x2, x3;
            ldsm4(a0, a1, a2, a3, aH + ko);
            ldsm4(x0, x1, x2, x3, aL + ko);
            uint32_t p0, p1, p2, p3, q0, q1, q2, q3;
            ldsm4(p0, p1, p2, p3, bH0 + ko);   // K hi, ntiles 0,1
            ldsm4(q0, q1, q2, q3, bH1 + ko);   // K hi, ntiles 2,3
            uint32_t r0, r1, r2, r3, s0, s1, s2, s3;
            ldsm4(r0, r1, r2, r3, bL0 + ko);   // K lo, ntiles 0,1
            ldsm4(s0, s1, s2, s3, bL1 + ko);   // K lo, ntiles 2,3

            mma16816(sc[0], a0, a1, a2, a3, p0, p1);
            mma16816(sc[1], a0, a1, a2, a3, p2, p3);
            mma16816(sc[2], a0, a1, a2, a3, q0, q1);
            mma16816(sc[3], a0, a1, a2, a3, q2, q3);
            mma16816(sc[0], a0, a1, a2, a3, r0, r1);
            mma16816(sc[1], a0, a1, a2, a3, r2, r3);
            mma16816(sc[2], a0, a1, a2, a3, s0, s1);
            mma16816(sc[3], a0, a1, a2, a3, s2, s3);
            mma16816(sc[0], x0, x1, x2, x3, p0, p1);
            mma16816(sc[1], x0, x1, x2, x3, p2, p3);
            mma16816(sc[2], x0, x1, x2, x3, q0, q1);
            mma16816(sc[3], x0, x1, x2, x3, q2, q3);
        }

        // V(it) fully arrived; all warps done reading sK
        CP_WAIT(0);
        __syncthreads();

        // prefetch K(it+1) — overlaps softmax + PV
        if (it + 1 < NTOK / BN) {
            load_tile32(sKh, Kh + (size_t)(it + 1) * BN * CCH, t);
            load_tile32(sKl, Kl + (size_t)(it + 1) * BN * CCH, t);
            CP_COMMIT();
        }

        // ---- online softmax (registers only; rows owned per-warp)
        float mx0 = fmaxf(fmaxf(sc[0][0], sc[0][1]), fmaxf(sc[1][0], sc[1][1]));
        mx0 = fmaxf(mx0, fmaxf(fmaxf(sc[2][0], sc[2][1]), fmaxf(sc[3][0], sc[3][1])));
        float mx1 = fmaxf(fmaxf(sc[0][2], sc[0][3]), fmaxf(sc[1][2], sc[1][3]));
        mx1 = fmaxf(mx1, fmaxf(fmaxf(sc[2][2], sc[2][3]), fmaxf(sc[3][2], sc[3][3])));
        mx0 = fmaxf(mx0, __shfl_xor_sync(0xffffffffu, mx0, 1));
        mx0 = fmaxf(mx0, __shfl_xor_sync(0xffffffffu, mx0, 2));
        mx1 = fmaxf(mx1, __shfl_xor_sync(0xffffffffu, mx1, 1));
        mx1 = fmaxf(mx1, __shfl_xor_sync(0xffffffffu, mx1, 2));
        const float mn0 = fmaxf(m0, mx0), mn1 = fmaxf(m1, mx1);
        const float f0 = __expf(m0 - mn0), f1 = __expf(m1 - mn1);
        m0 = mn0; m1 = mn1;

        uint32_t pa[2][4];
        float s0 = 0.0f, s1 = 0.0f;
        #pragma unroll
        for (int j = 0; j < 4; j++) {
            float e00 = __expf(sc[j][0] - mn0);
            float e01 = __expf(sc[j][1] - mn0);
            float e10 = __expf(sc[j][2] - mn1);
            float e11 = __expf(sc[j][3] - mn1);
            s0 += e00 + e01; s1 += e10 + e11;
            pa[j >> 1][(j & 1) * 2 + 0] = h2pack(e00, e01);
            pa[j >> 1][(j & 1) * 2 + 1] = h2pack(e10, e11);
        }
        s0 += __shfl_xor_sync(0xffffffffu, s0, 1);
        s0 += __shfl_xor_sync(0xffffffffu, s0, 2);
        s1 += __shfl_xor_sync(0xffffffffu, s1, 1);
        s1 += __shfl_xor_sync(0xffffffffu, s1, 2);
        l0 = l0 * f0 + s0;
        l1 = l1 * f1 + s1;

        #pragma unroll
        for (int nt = 0; nt < 32; nt++) {
            o[nt][0] *= f0; o[nt][1] *= f0;
            o[nt][2] *= f1; o[nt][3] *= f1;
        }

        // ---- PV: O[16 x 256] += P[16 x 32] * V[32 x 256]
        #pragma unroll
        for (int q = 0; q < 16; q++) {
            const uint32_t co = q * 32;   // 16 halves * 2B
            uint32_t v0, v1, v2, v3;
            ldsm4t(v0, v1, v2, v3, vB0 + co);       // key chunk 0, ch ntiles 2q,2q+1
            mma16816(o[2 * q + 0], pa[0][0], pa[0][1], pa[0][2], pa[0][3], v0, v1);
            mma16816(o[2 * q + 1], pa[0][0], pa[0][1], pa[0][2], pa[0][3], v2, v3);
            ldsm4t(v0, v1, v2, v3, vB1 + co);       // key chunk 1
            mma16816(o[2 * q + 0], pa[1][0], pa[1][1], pa[1][2], pa[1][3], v0, v1);
            mma16816(o[2 * q + 1], pa[1][0], pa[1][1], pa[1][2], pa[1][3], v2, v3);
        }

        __syncthreads();    // all warps done reading sV
        if (it + 1 < NTOK / BN) {
            load_tile32(sV, Vv + (size_t)(it + 1) * BN * CCH, t);
            CP_COMMIT();
            CP_WAIT(1);     // K(it+1) complete; V(it+1) may remain in flight
        }
        __syncthreads();    // K(it+1) visible to all warps
    }

    // ---- epilogue: O /= l, store fp32 Y[b][n][c]
    const float inv0 = 1.0f / l0, inv1 = 1.0f / l1;
    const int row0 = n0 + wr0 + (lane >> 2);
    float* __restrict__ Y0 = g_Y + ((size_t)b * NTOK + row0) * CCH + ((lane & 3) << 1);
    float* __restrict__ Y1 = Y0 + 8 * CCH;
    #pragma unroll
    for (int nt = 0; nt < 32; nt++) {
        float2 v0 = {o[nt][0] * inv0, o[nt][1] * inv0};
        float2 v1 = {o[nt][2] * inv1, o[nt][3] * inv1};
        *(float2*)(Y0 + nt * 8) = v0;
        *(float2*)(Y1 + nt * 8) = v1;
    }
}

// =============================================================================
// Kernel 3: out[b,c,n] = x[b,c,n] + gamma * sum_c' w_out[c,c'] * Y[b,n,c']
// =============================================================================
__global__ void out_kernel(const float* __restrict__ x,
                           const float* __restrict__ w_out,
                           const float* __restrict__ gamma,
                           float* __restrict__ out) {
    const int b  = blockIdx.z;
    const int n0 = blockIdx.x * 64;
    const int c0 = blockIdx.y * 64;

    __shared__ float As[16][64];
    __shared__ float Bs[16][64];

    const int t = threadIdx.x;
    const int tx = t & 15;
    const int ty = t >> 4;

    float acc[4][4] = {};
    const float* __restrict__ Yb = g_Y + (size_t)b * NTOK * CCH;

    for (int k0 = 0; k0 < CCH; k0 += 16) {
        __syncthreads();
        {
            const int cc = t & 63, kk4 = (t >> 6) * 4;
            float4 v = *(const float4*)&w_out[(size_t)(c0 + cc) * CCH + k0 + kk4];
            As[kk4 + 0][cc] = v.x; As[kk4 + 1][cc] = v.y;
            As[kk4 + 2][cc] = v.z; As[kk4 + 3][cc] = v.w;
        }
        {
            const int nn = t & 63, kk4 = (t >> 6) * 4;
            float4 v = *(const float4*)&Yb[(size_t)(n0 + nn) * CCH + k0 + kk4];
            Bs[kk4 + 0][nn] = v.x; Bs[kk4 + 1][nn] = v.y;
            Bs[kk4 + 2][nn] = v.z; Bs[kk4 + 3][nn] = v.w;
        }
        __syncthreads();
        #pragma unroll
        for (int kk = 0; kk < 16; kk++) {
            float4 a  = *(float4*)&As[kk][ty * 4];
            float4 bv = *(float4*)&Bs[kk][tx * 4];
            float av[4] = {a.x, a.y, a.z, a.w};
            float bw[4] = {bv.x, bv.y, bv.z, bv.w};
            #pragma unroll
            for (int i = 0; i < 4; i++)
                #pragma unroll
                for (int j = 0; j < 4; j++)
                    acc[i][j] += av[i] * bw[j];
        }
    }

    const float gm = *gamma;
    #pragma unroll
    for (int i = 0; i < 4; i++) {
        const int c = c0 + ty * 4 + i;
        const size_t idx = ((size_t)b * CCH + c) * NTOK + n0 + tx * 4;
        float4 xo = *(const float4*)&x[idx];
        float4 r;
        r.x = xo.x + gm * acc[i][0];
        r.y = xo.y + gm * acc[i][1];
        r.z = xo.z + gm * acc[i][2];
        r.w = xo.w + gm * acc[i][3];
        *(float4*)&out[idx] = r;
    }
}

// =============================================================================
extern "C" void kernel_launch(void* const* d_in, const int* in_sizes, int n_in,
                              void* d_out, int out_size) {
    (void)in_sizes; (void)n_in; (void)out_size;
    const float* x      = (const float*)d_in[0];
    const float* w_th   = (const float*)d_in[1];
    const float* w_ph   = (const float*)d_in[2];
    const float* w_g    = (const float*)d_in[3];
    const float* w_out  = (const float*)d_in[4];
    const float* gamma  = (const float*)d_in[5];
    float* out = (float*)d_out;

    const int smem_bytes = (2 * BM + 2 * BN + BN) * LDSH * 2;   // 185,856 B
    cudaFuncSetAttribute(flash_kernel, cudaFuncAttributeMaxDynamicSharedMemorySize,
                         smem_bytes);

    proj_kernel <<<dim3(NTOK / 64, CCH / 64, BSZ * 3), 256>>>(x, w_th, w_ph, w_g);
    flash_kernel<<<dim3(NTOK / BM, BSZ), 256, smem_bytes>>>();
    out_kernel  <<<dim3(NTOK / 64, CCH / 64, BSZ), 256>>>(x, w_out, gamma, out);
}

// round 3
// speedup vs baseline: 1.6237x; 1.2746x over previous
#include <cuda_runtime.h>
#include <cuda_fp16.h>
#include <cstdint>

#define BSZ  4
#define CCH  256
#define NTOK 4096

#define BM   128
#define BN   32
#define LDSH 264          // half elems per smem row (256 + 8 pad)

// ---------------- static device scratch (no allocation allowed) ----------------
__device__ __half g_th_hi[(size_t)BSZ * NTOK * CCH];
__device__ __half g_th_lo[(size_t)BSZ * NTOK * CCH];
__device__ __half g_ph_hi[(size_t)BSZ * NTOK * CCH];
__device__ __half g_ph_lo[(size_t)BSZ * NTOK * CCH];
__device__ __half g_gv  [(size_t)BSZ * NTOK * CCH];
__device__ __half g_y_hi[(size_t)BSZ * NTOK * CCH];
__device__ __half g_y_lo[(size_t)BSZ * NTOK * CCH];
__device__ __half g_x_hi[(size_t)BSZ * CCH * NTOK];
__device__ __half g_x_lo[(size_t)BSZ * CCH * NTOK];
__device__ __half g_w_hi[4 * CCH * CCH];
__device__ __half g_w_lo[4 * CCH * CCH];

// ---------------- PTX helpers ----------------
__device__ __forceinline__ uint32_t smem_u32(const void* p) {
    return (uint32_t)__cvta_generic_to_shared(p);
}
__device__ __forceinline__ void cp16(uint32_t s, const void* g) {
    asm volatile("cp.async.cg.shared.global [%0], [%1], 16;\n" :: "r"(s), "l"(g));
}
#define CP_COMMIT() asm volatile("cp.async.commit_group;\n" ::: "memory")
#define CP_WAIT(n)  asm volatile("cp.async.wait_group %0;\n" :: "n"(n) : "memory")

__device__ __forceinline__ void ldsm4(uint32_t& r0, uint32_t& r1, uint32_t& r2, uint32_t& r3,
                                      uint32_t a) {
    asm volatile("ldmatrix.sync.aligned.m8n8.x4.shared.b16 {%0,%1,%2,%3}, [%4];\n"
                 : "=r"(r0), "=r"(r1), "=r"(r2), "=r"(r3) : "r"(a));
}
__device__ __forceinline__ void ldsm4t(uint32_t& r0, uint32_t& r1, uint32_t& r2, uint32_t& r3,
                                       uint32_t a) {
    asm volatile("ldmatrix.sync.aligned.m8n8.x4.trans.shared.b16 {%0,%1,%2,%3}, [%4];\n"
                 : "=r"(r0), "=r"(r1), "=r"(r2), "=r"(r3) : "r"(a));
}
__device__ __forceinline__ void mma16816(float* c, uint32_t a0, uint32_t a1, uint32_t a2,
                                         uint32_t a3, uint32_t b0, uint32_t b1) {
    asm volatile("mma.sync.aligned.m16n8k16.row.col.f32.f16.f16.f32 "
                 "{%0,%1,%2,%3}, {%4,%5,%6,%7}, {%8,%9}, {%0,%1,%2,%3};\n"
                 : "+f"(c[0]), "+f"(c[1]), "+f"(c[2]), "+f"(c[3])
                 : "r"(a0), "r"(a1), "r"(a2), "r"(a3), "r"(b0), "r"(b1));
}
__device__ __forceinline__ uint32_t h2pack(float a, float b) {
    __half2 h = __floats2half2_rn(a, b);
    return *reinterpret_cast<uint32_t*>(&h);
}

__device__ __forceinline__ void load_tile32(__half* dst, const __half* src, int t) {
    #pragma unroll
    for (int i = 0; i < 4; i++) {
        int l = t + (i << 8);
        int r = l >> 5, c = (l & 31) << 3;
        cp16(smem_u32(dst + r * LDSH + c), src + (r << 8) + c);
    }
}

// =============================================================================
// Prep: split fp32 -> (hi, lo) fp16 pairs
// =============================================================================
__global__ void split_x_kernel(const float* __restrict__ x) {
    const int i = (blockIdx.x * 256 + threadIdx.x) * 4;
    float4 v = *(const float4*)&x[i];
    __half h0 = __float2half(v.x), h1 = __float2half(v.y);
    __half h2 = __float2half(v.z), h3 = __float2half(v.w);
    *(__half2*)&g_x_hi[i]     = __halves2half2(h0, h1);
    *(__half2*)&g_x_hi[i + 2] = __halves2half2(h2, h3);
    *(__half2*)&g_x_lo[i]     = __halves2half2(__float2half(v.x - __half2float(h0)),
                                               __float2half(v.y - __half2float(h1)));
    *(__half2*)&g_x_lo[i + 2] = __halves2half2(__float2half(v.z - __half2float(h2)),
                                               __float2half(v.w - __half2float(h3)));
}

__global__ void split_w_kernel(const float* __restrict__ w0, const float* __restrict__ w1,
                               const float* __restrict__ w2, const float* __restrict__ w3) {
    const int wsel = blockIdx.y;
    const float* __restrict__ w = (wsel == 0) ? w0 : (wsel == 1) ? w1 : (wsel == 2) ? w2 : w3;
    const int i = (blockIdx.x * 256 + threadIdx.x) * 4;
    const int o = wsel * CCH * CCH + i;
    float4 v = *(const float4*)&w[i];
    __half h0 = __float2half(v.x), h1 = __float2half(v.y);
    __half h2 = __float2half(v.z), h3 = __float2half(v.w);
    *(__half2*)&g_w_hi[o]     = __halves2half2(h0, h1);
    *(__half2*)&g_w_hi[o + 2] = __halves2half2(h2, h3);
    *(__half2*)&g_w_lo[o]     = __halves2half2(__float2half(v.x - __half2float(h0)),
                                               __float2half(v.y - __half2float(h1)));
    *(__half2*)&g_w_lo[o + 2] = __halves2half2(__float2half(v.z - __half2float(h2)),
                                               __float2half(v.w - __half2float(h3)));
}

// =============================================================================
// proj_tc: out[oc,n] = sum_c w[oc,c] * x[c,n]   split-fp16 tensor cores
// grid (NTOK/128, CCH/128, BSZ*3), 256 threads (8 warps: 4 m-groups x 2 n-groups)
// Epilogue transposes to [n][oc] layout (theta/phi hi+lo, g fp16).
// =============================================================================
#define PA_LD 40
#define PB_LD 136

__global__ void __launch_bounds__(256) proj_tc_kernel() {
    const int b  = blockIdx.z / 3;
    const int w  = blockIdx.z % 3;
    const int n0 = blockIdx.x * 128;
    const int m0 = blockIdx.y * 128;

    __shared__ __align__(16) char sm[38912];
    __half* sAh = (__half*)sm;                    // [128][40]
    __half* sAl = sAh + 128 * PA_LD;
    __half* sBh = (__half*)(sm + 20480);          // [32][136]
    __half* sBl = sBh + 32 * PB_LD;

    const int t    = threadIdx.x;
    const int lane = t & 31;
    const int warp = t >> 5;
    const int wr   = warp & 3;    // 32 oc rows
    const int wc   = warp >> 2;   // 64 n cols

    const __half* __restrict__ Ah = g_w_hi + w * CCH * CCH;
    const __half* __restrict__ Al = g_w_lo + w * CCH * CCH;
    const __half* __restrict__ Bh = g_x_hi + (size_t)b * CCH * NTOK;
    const __half* __restrict__ Bl = g_x_lo + (size_t)b * CCH * NTOK;

    float acc[2][8][4] = {};

    const int gi = lane >> 3, li = lane & 7;
    // A row-major frags
    const uint32_t aOff = (uint32_t)((wr * 32 + (lane & 15)) * PA_LD + ((lane >> 4) << 3)) * 2;
    // B col-major frags via trans ldsm from [k][n]
    const uint32_t bOff = (uint32_t)((((gi & 1) << 3) + li) * PB_LD
                                     + wc * 64 + ((gi >> 1) << 3)) * 2;
    const uint32_t sAh32 = smem_u32(sAh), sAl32 = smem_u32(sAl);
    const uint32_t sBh32 = smem_u32(sBh), sBl32 = smem_u32(sBl);

    for (int k0 = 0; k0 < CCH; k0 += 32) {
        __syncthreads();
        {   // A: 128 rows x 32k, hi+lo
            const int r = t >> 1, hoff = (t & 1) * 16;
            cp16(smem_u32(sAh + r * PA_LD + hoff),     Ah + (m0 + r) * CCH + k0 + hoff);
            cp16(smem_u32(sAh + r * PA_LD + hoff + 8), Ah + (m0 + r) * CCH + k0 + hoff + 8);
            cp16(smem_u32(sAl + r * PA_LD + hoff),     Al + (m0 + r) * CCH + k0 + hoff);
            cp16(smem_u32(sAl + r * PA_LD + hoff + 8), Al + (m0 + r) * CCH + k0 + hoff + 8);
        }
        {   // B: 32 k-rows x 128 n, hi+lo
            const int r = t >> 3, hoff = (t & 7) * 16;
            cp16(smem_u32(sBh + r * PB_LD + hoff),     Bh + (size_t)(k0 + r) * NTOK + n0 + hoff);
            cp16(smem_u32(sBh + r * PB_LD + hoff + 8), Bh + (size_t)(k0 + r) * NTOK + n0 + hoff + 8);
            cp16(smem_u32(sBl + r * PB_LD + hoff),     Bl + (size_t)(k0 + r) * NTOK + n0 + hoff);
            cp16(smem_u32(sBl + r * PB_LD + hoff + 8), Bl + (size_t)(k0 + r) * NTOK + n0 + hoff + 8);
        }
        CP_COMMIT();
        CP_WAIT(0);
        __syncthreads();

        #pragma unroll
        for (int ks = 0; ks < 2; ks++) {
            const uint32_t ka = ks * 32;               // 16 halves
            const uint32_t kb = ks * 16 * PB_LD * 2;   // 16 k-rows
            uint32_t ah[2][4], al[2][4];
            ldsm4(ah[0][0], ah[0][1], ah[0][2], ah[0][3], sAh32 + aOff + ka);
            ldsm4(ah[1][0], ah[1][1], ah[1][2], ah[1][3], sAh32 + aOff + ka + 16 * PA_LD * 2);
            ldsm4(al[0][0], al[0][1], al[0][2], al[0][3], sAl32 + aOff + ka);
            ldsm4(al[1][0], al[1][1], al[1][2], al[1][3], sAl32 + aOff + ka + 16 * PA_LD * 2);
            #pragma unroll
            for (int jn = 0; jn < 4; jn++) {
                uint32_t bhf[4], blf[4];
                ldsm4t(bhf[0], bhf[1], bhf[2], bhf[3], sBh32 + bOff + kb + jn * 32);
                ldsm4t(blf[0], blf[1], blf[2], blf[3], sBl32 + bOff + kb + jn * 32);
                #pragma unroll
                for (int mi = 0; mi < 2; mi++) {
                    mma16816(acc[mi][2 * jn + 0], ah[mi][0], ah[mi][1], ah[mi][2], ah[mi][3], bhf[0], bhf[1]);
                    mma16816(acc[mi][2 * jn + 1], ah[mi][0], ah[mi][1], ah[mi][2], ah[mi][3], bhf[2], bhf[3]);
                    mma16816(acc[mi][2 * jn + 0], ah[mi][0], ah[mi][1], ah[mi][2], ah[mi][3], blf[0], blf[1]);
                    mma16816(acc[mi][2 * jn + 1], ah[mi][0], ah[mi][1], ah[mi][2], ah[mi][3], blf[2], blf[3]);
                    mma16816(acc[mi][2 * jn + 0], al[mi][0], al[mi][1], al[mi][2], al[mi][3], bhf[0], bhf[1]);
                    mma16816(acc[mi][2 * jn + 1], al[mi][0], al[mi][1], al[mi][2], al[mi][3], bhf[2], bhf[3]);
                }
            }
        }
    }

    // ---- epilogue: transpose to [n][oc], split hi/lo (theta/phi) or fp16 (g)
    __half* buf = (__half*)sm;   // [128 n][136]
    const int mb = wr * 32 + (lane >> 2);
    const int nb = wc * 64 + (lane & 3) * 2;
    const int npass = (w == 2) ? 1 : 2;

    for (int pass = 0; pass < npass; pass++) {
        __syncthreads();
        #pragma unroll
        for (int mi = 0; mi < 2; mi++)
            #pragma unroll
            for (int jn = 0; jn < 8; jn++)
                #pragma unroll
                for (int e = 0; e < 4; e++) {
                    const float v = acc[mi][jn][e];
                    const int nl = nb + jn * 8 + (e & 1);
                    const int ml = mb + mi * 16 + ((e >> 1) << 3);
                    __half h = __float2half(v);
                    buf[nl * PB_LD + ml] =
                        (pass == 0) ? h : __float2half(v - __half2float(h));
                }
        __syncthreads();

        __half* __restrict__ G;
        if (w == 0) G = (pass == 0) ? g_th_hi : g_th_lo;
        else if (w == 1) G = (pass == 0) ? g_ph_hi : g_ph_lo;
        else G = g_gv;
        G += (size_t)b * NTOK * CCH;

        #pragma unroll
        for (int i = 0; i < 8; i++) {
            const int fi = t * 8 + i;
            const int row = fi >> 4, col8 = (fi & 15) * 8;
            *(float4*)&G[(size_t)(n0 + row) * CCH + m0 + col8] =
                *(float4*)&buf[row * PB_LD + col8];
        }
    }
}

// =============================================================================
// flash attention: Y = softmax(theta phi^T) g^T   (unchanged core, hi/lo Y out)
// =============================================================================
extern __shared__ char smem_raw[];

__global__ void __launch_bounds__(256, 1) flash_kernel() {
    const int b  = blockIdx.y;
    const int n0 = blockIdx.x * BM;

    __half* sQh = (__half*)smem_raw;
    __half* sQl = sQh + BM * LDSH;
    __half* sKh = sQl + BM * LDSH;
    __half* sKl = sKh + BN * LDSH;
    __half* sV  = sKl + BN * LDSH;

    const int t    = threadIdx.x;
    const int lane = t & 31;
    const int warp = t >> 5;
    const int wr0  = warp * 16;

    const __half* __restrict__ Qh = g_th_hi + ((size_t)b * NTOK + n0) * CCH;
    const __half* __restrict__ Ql = g_th_lo + ((size_t)b * NTOK + n0) * CCH;
    const __half* __restrict__ Kh = g_ph_hi + (size_t)b * NTOK * CCH;
    const __half* __restrict__ Kl = g_ph_lo + (size_t)b * NTOK * CCH;
    const __half* __restrict__ Vv = g_gv    + (size_t)b * NTOK * CCH;

    #pragma unroll
    for (int i = 0; i < 16; i++) {
        int l = t + (i << 8);
        int r = l >> 5, c = (l & 31) << 3;
        cp16(smem_u32(sQh + r * LDSH + c), Qh + (r << 8) + c);
        cp16(smem_u32(sQl + r * LDSH + c), Ql + (r << 8) + c);
    }
    load_tile32(sKh, Kh, t);
    load_tile32(sKl, Kl, t);
    load_tile32(sV,  Vv, t);
    CP_COMMIT();
    CP_WAIT(0);
    __syncthreads();

    const int gi = lane >> 3, li = lane & 7;
    const uint32_t aH = smem_u32(sQh + (wr0 + (lane & 15)) * LDSH + ((lane >> 4) << 3));
    const uint32_t aL = smem_u32(sQl + (wr0 + (lane & 15)) * LDSH + ((lane >> 4) << 3));
    const int bKey = ((gi >> 1) << 3) + li;
    const int bCh  = (gi & 1) << 3;
    const uint32_t bH0 = smem_u32(sKh + bKey * LDSH + bCh);
    const uint32_t bH1 = bH0 + 16 * LDSH * 2;
    const uint32_t bL0 = smem_u32(sKl + bKey * LDSH + bCh);
    const uint32_t bL1 = bL0 + 16 * LDSH * 2;
    const int vKey = ((gi & 1) << 3) + li;
    const int vCh  = (gi >> 1) << 3;
    const uint32_t vB0 = smem_u32(sV + vKey * LDSH + vCh);
    const uint32_t vB1 = vB0 + 16 * LDSH * 2;

    float o[32][4];
    #pragma unroll
    for (int nt = 0; nt < 32; nt++) { o[nt][0] = o[nt][1] = o[nt][2] = o[nt][3] = 0.0f; }
    float m0 = -1e30f, m1 = -1e30f, l0 = 0.0f, l1 = 0.0f;

    for (int it = 0; it < NTOK / BN; it++) {
        float sc[4][4];
        #pragma unroll
        for (int j = 0; j < 4; j++) sc[j][0] = sc[j][1] = sc[j][2] = sc[j][3] = 0.0f;

        #pragma unroll 4
        for (int kc = 0; kc < 16; kc++) {
            const uint32_t ko = kc * 32;
            uint32_t a0, a1, a2, a3, x0, x1, x2, x3;
            ldsm4(a0, a1, a2, a3, aH + ko);
            ldsm4(x0, x1, x2, x3, aL + ko);
            uint32_t p0, p1, p2, p3, q0, q1, q2, q3;
            ldsm4(p0, p1, p2, p3, bH0 + ko);
            ldsm4(q0, q1, q2, q3, bH1 + ko);
            uint32_t r0, r1, r2, r3, s0, s1, s2, s3;
            ldsm4(r0, r1, r2, r3, bL0 + ko);
            ldsm4(s0, s1, s2, s3, bL1 + ko);

            mma16816(sc[0], a0, a1, a2, a3, p0, p1);
            mma16816(sc[1], a0, a1, a2, a3, p2, p3);
            mma16816(sc[2], a0, a1, a2, a3, q0, q1);
            mma16816(sc[3], a0, a1, a2, a3, q2, q3);
            mma16816(sc[0], a0, a1, a2, a3, r0, r1);
            mma16816(sc[1], a0, a1, a2, a3, r2, r3);
            mma16816(sc[2], a0, a1, a2, a3, s0, s1);
            mma16816(sc[3], a0, a1, a2, a3, s2, s3);
            mma16816(sc[0], x0, x1, x2, x3, p0, p1);
            mma16816(sc[1], x0, x1, x2, x3, p2, p3);
            mma16816(sc[2], x0, x1, x2, x3, q0, q1);
            mma16816(sc[3], x0, x1, x2, x3, q2, q3);
        }

        CP_WAIT(0);
        __syncthreads();

        if (it + 1 < NTOK / BN) {
            load_tile32(sKh, Kh + (size_t)(it + 1) * BN * CCH, t);
            load_tile32(sKl, Kl + (size_t)(it + 1) * BN * CCH, t);
            CP_COMMIT();
        }

        float mx0 = fmaxf(fmaxf(sc[0][0], sc[0][1]), fmaxf(sc[1][0], sc[1][1]));
        mx0 = fmaxf(mx0, fmaxf(fmaxf(sc[2][0], sc[2][1]), fmaxf(sc[3][0], sc[3][1])));
        float mx1 = fmaxf(fmaxf(sc[0][2], sc[0][3]), fmaxf(sc[1][2], sc[1][3]));
        mx1 = fmaxf(mx1, fmaxf(fmaxf(sc[2][2], sc[2][3]), fmaxf(sc[3][2], sc[3][3])));
        mx0 = fmaxf(mx0, __shfl_xor_sync(0xffffffffu, mx0, 1));
        mx0 = fmaxf(mx0, __shfl_xor_sync(0xffffffffu, mx0, 2));
        mx1 = fmaxf(mx1, __shfl_xor_sync(0xffffffffu, mx1, 1));
        mx1 = fmaxf(mx1, __shfl_xor_sync(0xffffffffu, mx1, 2));
        const float mn0 = fmaxf(m0, mx0), mn1 = fmaxf(m1, mx1);
        const float f0 = __expf(m0 - mn0), f1 = __expf(m1 - mn1);
        m0 = mn0; m1 = mn1;

        uint32_t pa[2][4];
        float s0 = 0.0f, s1 = 0.0f;
        #pragma unroll
        for (int j = 0; j < 4; j++) {
            float e00 = __expf(sc[j][0] - mn0);
            float e01 = __expf(sc[j][1] - mn0);
            float e10 = __expf(sc[j][2] - mn1);
            float e11 = __expf(sc[j][3] - mn1);
            s0 += e00 + e01; s1 += e10 + e11;
            pa[j >> 1][(j & 1) * 2 + 0] = h2pack(e00, e01);
            pa[j >> 1][(j & 1) * 2 + 1] = h2pack(e10, e11);
        }
        s0 += __shfl_xor_sync(0xffffffffu, s0, 1);
        s0 += __shfl_xor_sync(0xffffffffu, s0, 2);
        s1 += __shfl_xor_sync(0xffffffffu, s1, 1);
        s1 += __shfl_xor_sync(0xffffffffu, s1, 2);
        l0 = l0 * f0 + s0;
        l1 = l1 * f1 + s1;

        #pragma unroll
        for (int nt = 0; nt < 32; nt++) {
            o[nt][0] *= f0; o[nt][1] *= f0;
            o[nt][2] *= f1; o[nt][3] *= f1;
        }

        #pragma unroll
        for (int q = 0; q < 16; q++) {
            const uint32_t co = q * 32;
            uint32_t v0, v1, v2, v3;
            ldsm4t(v0, v1, v2, v3, vB0 + co);
            mma16816(o[2 * q + 0], pa[0][0], pa[0][1], pa[0][2], pa[0][3], v0, v1);
            mma16816(o[2 * q + 1], pa[0][0], pa[0][1], pa[0][2], pa[0][3], v2, v3);
            ldsm4t(v0, v1, v2, v3, vB1 + co);
            mma16816(o[2 * q + 0], pa[1][0], pa[1][1], pa[1][2], pa[1][3], v0, v1);
            mma16816(o[2 * q + 1], pa[1][0], pa[1][1], pa[1][2], pa[1][3], v2, v3);
        }

        __syncthreads();
        if (it + 1 < NTOK / BN) {
            load_tile32(sV, Vv + (size_t)(it + 1) * BN * CCH, t);
            CP_COMMIT();
            CP_WAIT(1);
        }
        __syncthreads();
    }

    // ---- epilogue: O /= l, store as hi/lo fp16 pair (exact split)
    const float inv0 = 1.0f / l0, inv1 = 1.0f / l1;
    const int row0 = n0 + wr0 + (lane >> 2);
    const size_t base = ((size_t)b * NTOK + row0) * CCH + ((lane & 3) << 1);
    __half* __restrict__ Yh0 = g_y_hi + base;
    __half* __restrict__ Yl0 = g_y_lo + base;
    #pragma unroll
    for (int nt = 0; nt < 32; nt++) {
        float v0 = o[nt][0] * inv0, v1 = o[nt][1] * inv0;
        float v2 = o[nt][2] * inv1, v3 = o[nt][3] * inv1;
        __half h0 = __float2half(v0), h1 = __float2half(v1);
        __half h2 = __float2half(v2), h3 = __float2half(v3);
        *(__half2*)(Yh0 + nt * 8)            = __halves2half2(h0, h1);
        *(__half2*)(Yh0 + nt * 8 + 8 * CCH)  = __halves2half2(h2, h3);
        *(__half2*)(Yl0 + nt * 8)            = __halves2half2(__float2half(v0 - __half2float(h0)),
                                                              __float2half(v1 - __half2float(h1)));
        *(__half2*)(Yl0 + nt * 8 + 8 * CCH)  = __halves2half2(__float2half(v2 - __half2float(h2)),
                                                              __float2half(v3 - __half2float(h3)));
    }
}

// =============================================================================
// out_tc: out[b,oc,n] = x[b,oc,n] + gamma * sum_c w_out[oc,c] * Y[b,n,c]
// grid (NTOK/128, CCH/128, BSZ), 256 threads
// =============================================================================
__global__ void __launch_bounds__(256) out_tc_kernel(const float* __restrict__ x,
                                                     const float* __restrict__ gamma,
                                                     float* __restrict__ out) {
    const int b  = blockIdx.z;
    const int n0 = blockIdx.x * 128;
    const int m0 = blockIdx.y * 128;

    __shared__ __align__(16) __half sAh[128 * PA_LD];
    __shared__ __align__(16) __half sAl[128 * PA_LD];
    __shared__ __align__(16) __half sBh[128 * PA_LD];
    __shared__ __align__(16) __half sBl[128 * PA_LD];

    const int t    = threadIdx.x;
    const int lane = t & 31;
    const int warp = t >> 5;
    const int wr   = warp & 3;
    const int wc   = warp >> 2;

    const __half* __restrict__ Ah = g_w_hi + 3 * CCH * CCH;
    const __half* __restrict__ Al = g_w_lo + 3 * CCH * CCH;
    const __half* __restrict__ Bh = g_y_hi + (size_t)b * NTOK * CCH;
    const __half* __restrict__ Bl = g_y_lo + (size_t)b * NTOK * CCH;

    float acc[2][8][4] = {};

    const int gi = lane >> 3, li = lane & 7;
    const uint32_t aOff = (uint32_t)((wr * 32 + (lane & 15)) * PA_LD + ((lane >> 4) << 3)) * 2;
    // B frags: plain ldsm from [n][k] (flash QK-B pattern), warp n-range = wc*64
    const uint32_t bOff = (uint32_t)((wc * 64 + ((gi >> 1) << 3) + li) * PA_LD
                                     + ((gi & 1) << 3)) * 2;
    const uint32_t sAh32 = smem_u32(sAh), sAl32 = smem_u32(sAl);
    const uint32_t sBh32 = smem_u32(sBh), sBl32 = smem_u32(sBl);

    for (int k0 = 0; k0 < CCH; k0 += 32) {
        __syncthreads();
        {
            const int r = t >> 1, hoff = (t & 1) * 16;
            cp16(smem_u32(sAh + r * PA_LD + hoff),     Ah + (m0 + r) * CCH + k0 + hoff);
            cp16(smem_u32(sAh + r * PA_LD + hoff + 8), Ah + (m0 + r) * CCH + k0 + hoff + 8);
            cp16(smem_u32(sAl + r * PA_LD + hoff),     Al + (m0 + r) * CCH + k0 + hoff);
            cp16(smem_u32(sAl + r * PA_LD + hoff + 8), Al + (m0 + r) * CCH + k0 + hoff + 8);
            cp16(smem_u32(sBh + r * PA_LD + hoff),     Bh + (size_t)(n0 + r) * CCH + k0 + hoff);
            cp16(smem_u32(sBh + r * PA_LD + hoff + 8), Bh + (size_t)(n0 + r) * CCH + k0 + hoff + 8);
            cp16(smem_u32(sBl + r * PA_LD + hoff),     Bl + (size_t)(n0 + r) * CCH + k0 + hoff);
            cp16(smem_u32(sBl + r * PA_LD + hoff + 8), Bl + (size_t)(n0 + r) * CCH + k0 + hoff + 8);
        }
        CP_COMMIT();
        CP_WAIT(0);
        __syncthreads();

        #pragma unroll
        for (int ks = 0; ks < 2; ks++) {
            const uint32_t ka = ks * 32;
            uint32_t ah[2][4], al[2][4];
            ldsm4(ah[0][0], ah[0][1], ah[0][2], ah[0][3], sAh32 + aOff + ka);
            ldsm4(ah[1][0], ah[1][1], ah[1][2], ah[1][3], sAh32 + aOff + ka + 16 * PA_LD * 2);
            ldsm4(al[0][0], al[0][1], al[0][2], al[0][3], sAl32 + aOff + ka);
            ldsm4(al[1][0], al[1][1], al[1][2], al[1][3], sAl32 + aOff + ka + 16 * PA_LD * 2);
            #pragma unroll
            for (int jn = 0; jn < 4; jn++) {
                uint32_t bhf[4], blf[4];
                ldsm4(bhf[0], bhf[1], bhf[2], bhf[3], sBh32 + bOff + ka + jn * 16 * PA_LD * 2);
                ldsm4(blf[0], blf[1], blf[2], blf[3], sBl32 + bOff + ka + jn * 16 * PA_LD * 2);
                #pragma unroll
                for (int mi = 0; mi < 2; mi++) {
                    mma16816(acc[mi][2 * jn + 0], ah[mi][0], ah[mi][1], ah[mi][2], ah[mi][3], bhf[0], bhf[1]);
                    mma16816(acc[mi][2 * jn + 1], ah[mi][0], ah[mi][1], ah[mi][2], ah[mi][3], bhf[2], bhf[3]);
                    mma16816(acc[mi][2 * jn + 0], ah[mi][0], ah[mi][1], ah[mi][2], ah[mi][3], blf[0], blf[1]);
                    mma16816(acc[mi][2 * jn + 1], ah[mi][0], ah[mi][1], ah[mi][2], ah[mi][3], blf[2], blf[3]);
                    mma16816(acc[mi][2 * jn + 0], al[mi][0], al[mi][1], al[mi][2], al[mi][3], bhf[0], bhf[1]);
                    mma16816(acc[mi][2 * jn + 1], al[mi][0], al[mi][1], al[mi][2], al[mi][3], bhf[2], bhf[3]);
                }
            }
        }
    }

    // ---- epilogue: out = x + gamma*att, accumulators map directly to [oc][n]
    const float gm = *gamma;
    const int mb = m0 + wr * 32 + (lane >> 2);
    const int nb = n0 + wc * 64 + (lane & 3) * 2;
    #pragma unroll
    for (int mi = 0; mi < 2; mi++)
        #pragma unroll
        for (int jn = 0; jn < 8; jn++) {
            const int m = mb + mi * 16;
            const int n = nb + jn * 8;
            {
                const size_t idx = ((size_t)b * CCH + m) * NTOK + n;
                float2 xv = *(const float2*)&x[idx];
                float2 r = {xv.x + gm * acc[mi][jn][0], xv.y + gm * acc[mi][jn][1]};
                *(float2*)&out[idx] = r;
            }
            {
                const size_t idx = ((size_t)b * CCH + m + 8) * NTOK + n;
                float2 xv = *(const float2*)&x[idx];
                float2 r = {xv.x + gm * acc[mi][jn][2], xv.y + gm * acc[mi][jn][3]};
                *(float2*)&out[idx] = r;
            }
        }
}

// =============================================================================
extern "C" void kernel_launch(void* const* d_in, const int* in_sizes, int n_in,
                              void* d_out, int out_size) {
    (void)in_sizes; (void)n_in; (void)out_size;
    const float* x      = (const float*)d_in[0];
    const float* w_th   = (const float*)d_in[1];
    const float* w_ph   = (const float*)d_in[2];
    const float* w_g    = (const float*)d_in[3];
    const float* w_out  = (const float*)d_in[4];
    const float* gamma  = (const float*)d_in[5];
    float* out = (float*)d_out;

    const int smem_bytes = (2 * BM + 2 * BN + BN) * LDSH * 2;
    cudaFuncSetAttribute(flash_kernel, cudaFuncAttributeMaxDynamicSharedMemorySize,
                         smem_bytes);

    split_x_kernel<<<(BSZ * CCH * NTOK) / 1024, 256>>>(x);
    split_w_kernel<<<dim3(64, 4), 256>>>(w_th, w_ph, w_g, w_out);
    proj_tc_kernel<<<dim3(NTOK / 128, CCH / 128, BSZ * 3), 256>>>();
    flash_kernel  <<<dim3(NTOK / BM, BSZ), 256, smem_bytes>>>();
    out_tc_kernel <<<dim3(NTOK / 128, CCH / 128, BSZ), 256>>>(x, gamma, out);
}

// round 4
// speedup vs baseline: 1.7942x; 1.1050x over previous
#include <cuda_runtime.h>
#include <cuda_fp16.h>
#include <cstdint>

#define BSZ  4
#define CCH  256
#define NTOK 4096

#define BM   128
#define BN   64

// ---------------- static device scratch (no allocation allowed) ----------------
__device__ __half g_th_hi[(size_t)BSZ * NTOK * CCH];
__device__ __half g_th_lo[(size_t)BSZ * NTOK * CCH];
__device__ __half g_ph_hi[(size_t)BSZ * NTOK * CCH];
__device__ __half g_ph_lo[(size_t)BSZ * NTOK * CCH];
__device__ __half g_gv  [(size_t)BSZ * NTOK * CCH];
__device__ __half g_y_hi[(size_t)BSZ * NTOK * CCH];
__device__ __half g_y_lo[(size_t)BSZ * NTOK * CCH];
__device__ __half g_x_hi[(size_t)BSZ * CCH * NTOK];
__device__ __half g_x_lo[(size_t)BSZ * CCH * NTOK];
__device__ __half g_w_hi[4 * CCH * CCH];
__device__ __half g_w_lo[4 * CCH * CCH];

// ---------------- PTX helpers ----------------
__device__ __forceinline__ uint32_t smem_u32(const void* p) {
    return (uint32_t)__cvta_generic_to_shared(p);
}
__device__ __forceinline__ void cp16(uint32_t s, const void* g) {
    asm volatile("cp.async.cg.shared.global [%0], [%1], 16;\n" :: "r"(s), "l"(g));
}
#define CP_COMMIT() asm volatile("cp.async.commit_group;\n" ::: "memory")
#define CP_WAIT(n)  asm volatile("cp.async.wait_group %0;\n" :: "n"(n) : "memory")

__device__ __forceinline__ void ldsm4(uint32_t& r0, uint32_t& r1, uint32_t& r2, uint32_t& r3,
                                      uint32_t a) {
    asm volatile("ldmatrix.sync.aligned.m8n8.x4.shared.b16 {%0,%1,%2,%3}, [%4];\n"
                 : "=r"(r0), "=r"(r1), "=r"(r2), "=r"(r3) : "r"(a));
}
__device__ __forceinline__ void ldsm4t(uint32_t& r0, uint32_t& r1, uint32_t& r2, uint32_t& r3,
                                       uint32_t a) {
    asm volatile("ldmatrix.sync.aligned.m8n8.x4.trans.shared.b16 {%0,%1,%2,%3}, [%4];\n"
                 : "=r"(r0), "=r"(r1), "=r"(r2), "=r"(r3) : "r"(a));
}
__device__ __forceinline__ void mma16816(float* c, uint32_t a0, uint32_t a1, uint32_t a2,
                                         uint32_t a3, uint32_t b0, uint32_t b1) {
    asm volatile("mma.sync.aligned.m16n8k16.row.col.f32.f16.f16.f32 "
                 "{%0,%1,%2,%3}, {%4,%5,%6,%7}, {%8,%9}, {%0,%1,%2,%3};\n"
                 : "+f"(c[0]), "+f"(c[1]), "+f"(c[2]), "+f"(c[3])
                 : "r"(a0), "r"(a1), "r"(a2), "r"(a3), "r"(b0), "r"(b1));
}
__device__ __forceinline__ uint32_t h2pack(float a, float b) {
    __half2 h = __floats2half2_rn(a, b);
    return *reinterpret_cast<uint32_t*>(&h);
}

// ---- swizzled tile loaders: row stride 512B, 16B chunk c stored at (c ^ (row&7))
__device__ __forceinline__ void load_tile64_sw(char* dst, const __half* src, int t) {
    #pragma unroll
    for (int i = 0; i < 8; i++) {
        int idx = t + (i << 8);
        int r = idx >> 5, c = idx & 31;
        cp16(smem_u32(dst + r * 512 + ((c ^ (r & 7)) << 4)), src + (r << 8) + (c << 3));
    }
}
__device__ __forceinline__ void load_tile128_sw(char* dst, const __half* src, int t) {
    #pragma unroll
    for (int i = 0; i < 16; i++) {
        int idx = t + (i << 8);
        int r = idx >> 5, c = idx & 31;
        cp16(smem_u32(dst + r * 512 + ((c ^ (r & 7)) << 4)), src + (r << 8) + (c << 3));
    }
}

// =============================================================================
// Prep: split fp32 -> (hi, lo) fp16 pairs
// =============================================================================
__global__ void split_x_kernel(const float* __restrict__ x) {
    const int i = (blockIdx.x * 256 + threadIdx.x) * 4;
    float4 v = *(const float4*)&x[i];
    __half h0 = __float2half(v.x), h1 = __float2half(v.y);
    __half h2 = __float2half(v.z), h3 = __float2half(v.w);
    *(__half2*)&g_x_hi[i]     = __halves2half2(h0, h1);
    *(__half2*)&g_x_hi[i + 2] = __halves2half2(h2, h3);
    *(__half2*)&g_x_lo[i]     = __halves2half2(__float2half(v.x - __half2float(h0)),
                                               __float2half(v.y - __half2float(h1)));
    *(__half2*)&g_x_lo[i + 2] = __halves2half2(__float2half(v.z - __half2float(h2)),
                                               __float2half(v.w - __half2float(h3)));
}

__global__ void split_w_kernel(const float* __restrict__ w0, const float* __restrict__ w1,
                               const float* __restrict__ w2, const float* __restrict__ w3) {
    const int wsel = blockIdx.y;
    const float* __restrict__ w = (wsel == 0) ? w0 : (wsel == 1) ? w1 : (wsel == 2) ? w2 : w3;
    const int i = (blockIdx.x * 256 + threadIdx.x) * 4;
    const int o = wsel * CCH * CCH + i;
    float4 v = *(const float4*)&w[i];
    __half h0 = __float2half(v.x), h1 = __float2half(v.y);
    __half h2 = __float2half(v.z), h3 = __float2half(v.w);
    *(__half2*)&g_w_hi[o]     = __halves2half2(h0, h1);
    *(__half2*)&g_w_hi[o + 2] = __halves2half2(h2, h3);
    *(__half2*)&g_w_lo[o]     = __halves2half2(__float2half(v.x - __half2float(h0)),
                                               __float2half(v.y - __half2float(h1)));
    *(__half2*)&g_w_lo[o + 2] = __halves2half2(__float2half(v.z - __half2float(h2)),
                                               __float2half(v.w - __half2float(h3)));
}

// =============================================================================
// proj_tc: out[oc,n] = sum_c w[oc,c] * x[c,n]   split-fp16 tensor cores
// =============================================================================
#define PA_LD 40
#define PB_LD 136

__global__ void __launch_bounds__(256) proj_tc_kernel() {
    const int b  = blockIdx.z / 3;
    const int w  = blockIdx.z % 3;
    const int n0 = blockIdx.x * 128;
    const int m0 = blockIdx.y * 128;

    __shared__ __align__(16) char sm[38912];
    __half* sAh = (__half*)sm;                    // [128][40]
    __half* sAl = sAh + 128 * PA_LD;
    __half* sBh = (__half*)(sm + 20480);          // [32][136]
    __half* sBl = sBh + 32 * PB_LD;

    const int t    = threadIdx.x;
    const int lane = t & 31;
    const int warp = t >> 5;
    const int wr   = warp & 3;
    const int wc   = warp >> 2;

    const __half* __restrict__ Ah = g_w_hi + w * CCH * CCH;
    const __half* __restrict__ Al = g_w_lo + w * CCH * CCH;
    const __half* __restrict__ Bh = g_x_hi + (size_t)b * CCH * NTOK;
    const __half* __restrict__ Bl = g_x_lo + (size_t)b * CCH * NTOK;

    float acc[2][8][4] = {};

    const int gi = lane >> 3, li = lane & 7;
    const uint32_t aOff = (uint32_t)((wr * 32 + (lane & 15)) * PA_LD + ((lane >> 4) << 3)) * 2;
    const uint32_t bOff = (uint32_t)((((gi & 1) << 3) + li) * PB_LD
                                     + wc * 64 + ((gi >> 1) << 3)) * 2;
    const uint32_t sAh32 = smem_u32(sAh), sAl32 = smem_u32(sAl);
    const uint32_t sBh32 = smem_u32(sBh), sBl32 = smem_u32(sBl);

    for (int k0 = 0; k0 < CCH; k0 += 32) {
        __syncthreads();
        {
            const int r = t >> 1, hoff = (t & 1) * 16;
            cp16(smem_u32(sAh + r * PA_LD + hoff),     Ah + (m0 + r) * CCH + k0 + hoff);
            cp16(smem_u32(sAh + r * PA_LD + hoff + 8), Ah + (m0 + r) * CCH + k0 + hoff + 8);
            cp16(smem_u32(sAl + r * PA_LD + hoff),     Al + (m0 + r) * CCH + k0 + hoff);
            cp16(smem_u32(sAl + r * PA_LD + hoff + 8), Al + (m0 + r) * CCH + k0 + hoff + 8);
        }
        {
            const int r = t >> 3, hoff = (t & 7) * 16;
            cp16(smem_u32(sBh + r * PB_LD + hoff),     Bh + (size_t)(k0 + r) * NTOK + n0 + hoff);
            cp16(smem_u32(sBh + r * PB_LD + hoff + 8), Bh + (size_t)(k0 + r) * NTOK + n0 + hoff + 8);
            cp16(smem_u32(sBl + r * PB_LD + hoff),     Bl + (size_t)(k0 + r) * NTOK + n0 + hoff);
            cp16(smem_u32(sBl + r * PB_LD + hoff + 8), Bl + (size_t)(k0 + r) * NTOK + n0 + hoff + 8);
        }
        CP_COMMIT();
        CP_WAIT(0);
        __syncthreads();

        #pragma unroll
        for (int ks = 0; ks < 2; ks++) {
            const uint32_t ka = ks * 32;
            const uint32_t kb = ks * 16 * PB_LD * 2;
            uint32_t ah[2][4], al[2][4];
            ldsm4(ah[0][0], ah[0][1], ah[0][2], ah[0][3], sAh32 + aOff + ka);
            ldsm4(ah[1][0], ah[1][1], ah[1][2], ah[1][3], sAh32 + aOff + ka + 16 * PA_LD * 2);
            ldsm4(al[0][0], al[0][1], al[0][2], al[0][3], sAl32 + aOff + ka);
            ldsm4(al[1][0], al[1][1], al[1][2], al[1][3], sAl32 + aOff + ka + 16 * PA_LD * 2);
            #pragma unroll
            for (int jn = 0; jn < 4; jn++) {
                uint32_t bhf[4], blf[4];
                ldsm4t(bhf[0], bhf[1], bhf[2], bhf[3], sBh32 + bOff + kb + jn * 32);
                ldsm4t(blf[0], blf[1], blf[2], blf[3], sBl32 + bOff + kb + jn * 32);
                #pragma unroll
                for (int mi = 0; mi < 2; mi++) {
                    mma16816(acc[mi][2 * jn + 0], ah[mi][0], ah[mi][1], ah[mi][2], ah[mi][3], bhf[0], bhf[1]);
                    mma16816(acc[mi][2 * jn + 1], ah[mi][0], ah[mi][1], ah[mi][2], ah[mi][3], bhf[2], bhf[3]);
                    mma16816(acc[mi][2 * jn + 0], ah[mi][0], ah[mi][1], ah[mi][2], ah[mi][3], blf[0], blf[1]);
                    mma16816(acc[mi][2 * jn + 1], ah[mi][0], ah[mi][1], ah[mi][2], ah[mi][3], blf[2], blf[3]);
                    mma16816(acc[mi][2 * jn + 0], al[mi][0], al[mi][1], al[mi][2], al[mi][3], bhf[0], bhf[1]);
                    mma16816(acc[mi][2 * jn + 1], al[mi][0], al[mi][1], al[mi][2], al[mi][3], bhf[2], bhf[3]);
                }
            }
        }
    }

    __half* buf = (__half*)sm;   // [128 n][136]
    const int mb = wr * 32 + (lane >> 2);
    const int nb = wc * 64 + (lane & 3) * 2;
    const int npass = (w == 2) ? 1 : 2;

    for (int pass = 0; pass < npass; pass++) {
        __syncthreads();
        #pragma unroll
        for (int mi = 0; mi < 2; mi++)
            #pragma unroll
            for (int jn = 0; jn < 8; jn++)
                #pragma unroll
                for (int e = 0; e < 4; e++) {
                    const float v = acc[mi][jn][e];
                    const int nl = nb + jn * 8 + (e & 1);
                    const int ml = mb + mi * 16 + ((e >> 1) << 3);
                    __half h = __float2half(v);
                    buf[nl * PB_LD + ml] =
                        (pass == 0) ? h : __float2half(v - __half2float(h));
                }
        __syncthreads();

        __half* __restrict__ G;
        if (w == 0) G = (pass == 0) ? g_th_hi : g_th_lo;
        else if (w == 1) G = (pass == 0) ? g_ph_hi : g_ph_lo;
        else G = g_gv;
        G += (size_t)b * NTOK * CCH;

        #pragma unroll
        for (int i = 0; i < 8; i++) {
            const int fi = t * 8 + i;
            const int row = fi >> 4, col8 = (fi & 15) * 8;
            *(float4*)&G[(size_t)(n0 + row) * CCH + m0 + col8] =
                *(float4*)&buf[row * PB_LD + col8];
        }
    }
}

// =============================================================================
// flash attention, BN=64, swizzled smem, skip-rescale
// grid (NTOK/BM, BSZ), 256 threads (8 warps x 16 query rows)
// =============================================================================
extern __shared__ char smem_raw[];

__global__ void __launch_bounds__(256, 1) flash_kernel() {
    const int b  = blockIdx.y;
    const int n0 = blockIdx.x * BM;

    char* sQh = smem_raw;                 // 128 x 512B
    char* sQl = smem_raw + 65536;
    char* sKh = smem_raw + 131072;        // 64 x 512B
    char* sKl = smem_raw + 163840;
    char* sV  = smem_raw + 196608;

    const int t    = threadIdx.x;
    const int lane = t & 31;
    const int warp = t >> 5;
    const int wr0  = warp * 16;

    const __half* __restrict__ Qh = g_th_hi + ((size_t)b * NTOK + n0) * CCH;
    const __half* __restrict__ Ql = g_th_lo + ((size_t)b * NTOK + n0) * CCH;
    const __half* __restrict__ Kh = g_ph_hi + (size_t)b * NTOK * CCH;
    const __half* __restrict__ Kl = g_ph_lo + (size_t)b * NTOK * CCH;
    const __half* __restrict__ Vv = g_gv    + (size_t)b * NTOK * CCH;

    load_tile128_sw(sQh, Qh, t);
    load_tile128_sw(sQl, Ql, t);
    load_tile64_sw(sKh, Kh, t);
    load_tile64_sw(sKl, Kl, t);
    load_tile64_sw(sV,  Vv, t);
    CP_COMMIT();
    CP_WAIT(0);
    __syncthreads();

    // ---- per-lane ldsm bases (swizzled: chunk' = chunk ^ (row & 7))
    const int gi = lane >> 3, li = lane & 7;
    const int arow = wr0 + (lane & 15);
    const uint32_t aSw = (uint32_t)(arow & 7);
    const uint32_t aS0 = (uint32_t)(lane >> 4);
    const uint32_t aHrb = smem_u32(sQh + arow * 512);
    const uint32_t aLrb = smem_u32(sQl + arow * 512);

    const int brow = ((gi >> 1) << 3) + li;        // key row within 16-block
    const uint32_t bSw = (uint32_t)(brow & 7);
    const uint32_t bS  = (uint32_t)(gi & 1);
    const uint32_t bHrb = smem_u32(sKh + brow * 512);
    const uint32_t bLrb = smem_u32(sKl + brow * 512);

    const int vrow = ((gi & 1) << 3) + li;
    const uint32_t vSw = (uint32_t)(vrow & 7);
    const uint32_t vS  = (uint32_t)(gi >> 1);
    const uint32_t vrb = smem_u32(sV + vrow * 512);

    float o[32][4];
    #pragma unroll
    for (int nt = 0; nt < 32; nt++) { o[nt][0] = o[nt][1] = o[nt][2] = o[nt][3] = 0.0f; }
    float m0 = -1e30f, m1 = -1e30f, l0 = 0.0f, l1 = 0.0f;

    for (int it = 0; it < NTOK / BN; it++) {
        // ---- QK: S[16 x 64] per warp, split-fp16 (3 terms)
        float sc[8][4];
        #pragma unroll
        for (int j = 0; j < 8; j++) sc[j][0] = sc[j][1] = sc[j][2] = sc[j][3] = 0.0f;

        #pragma unroll 4
        for (int kc = 0; kc < 16; kc++) {
            const uint32_t offA = (((2 * kc + aS0) ^ aSw) << 4);
            uint32_t ah0, ah1, ah2, ah3, al0, al1, al2, al3;
            ldsm4(ah0, ah1, ah2, ah3, aHrb + offA);
            ldsm4(al0, al1, al2, al3, aLrb + offA);
            const uint32_t offB = (((2 * kc + bS) ^ bSw) << 4);
            #pragma unroll
            for (int kk = 0; kk < 4; kk++) {
                uint32_t bh0, bh1, bh2, bh3, bl0, bl1, bl2, bl3;
                ldsm4(bh0, bh1, bh2, bh3, bHrb + kk * 8192 + offB);
                ldsm4(bl0, bl1, bl2, bl3, bLrb + kk * 8192 + offB);
                mma16816(sc[2 * kk + 0], ah0, ah1, ah2, ah3, bh0, bh1);
                mma16816(sc[2 * kk + 1], ah0, ah1, ah2, ah3, bh2, bh3);
                mma16816(sc[2 * kk + 0], ah0, ah1, ah2, ah3, bl0, bl1);
                mma16816(sc[2 * kk + 1], ah0, ah1, ah2, ah3, bl2, bl3);
                mma16816(sc[2 * kk + 0], al0, al1, al2, al3, bh0, bh1);
                mma16816(sc[2 * kk + 1], al0, al1, al2, al3, bh2, bh3);
            }
        }

        CP_WAIT(0);           // V(it) complete
        __syncthreads();      // all warps done reading sK

        if (it + 1 < NTOK / BN) {
            load_tile64_sw(sKh, Kh + (size_t)(it + 1) * BN * CCH, t);
            load_tile64_sw(sKl, Kl + (size_t)(it + 1) * BN * CCH, t);
            CP_COMMIT();
        }

        // ---- online softmax
        float mx0 = -1e30f, mx1 = -1e30f;
        #pragma unroll
        for (int j = 0; j < 8; j++) {
            mx0 = fmaxf(mx0, fmaxf(sc[j][0], sc[j][1]));
            mx1 = fmaxf(mx1, fmaxf(sc[j][2], sc[j][3]));
        }
        mx0 = fmaxf(mx0, __shfl_xor_sync(0xffffffffu, mx0, 1));
        mx0 = fmaxf(mx0, __shfl_xor_sync(0xffffffffu, mx0, 2));
        mx1 = fmaxf(mx1, __shfl_xor_sync(0xffffffffu, mx1, 1));
        mx1 = fmaxf(mx1, __shfl_xor_sync(0xffffffffu, mx1, 2));
        const bool upd = (mx0 > m0) || (mx1 > m1);
        const float mn0 = fmaxf(m0, mx0), mn1 = fmaxf(m1, mx1);
        const float f0 = __expf(m0 - mn0), f1 = __expf(m1 - mn1);
        m0 = mn0; m1 = mn1;

        uint32_t pa[4][4];
        float s0 = 0.0f, s1 = 0.0f;
        #pragma unroll
        for (int j = 0; j < 8; j++) {
            float e00 = __expf(sc[j][0] - mn0);
            float e01 = __expf(sc[j][1] - mn0);
            float e10 = __expf(sc[j][2] - mn1);
            float e11 = __expf(sc[j][3] - mn1);
            s0 += e00 + e01; s1 += e10 + e11;
            pa[j >> 1][(j & 1) * 2 + 0] = h2pack(e00, e01);
            pa[j >> 1][(j & 1) * 2 + 1] = h2pack(e10, e11);
        }
        s0 += __shfl_xor_sync(0xffffffffu, s0, 1);
        s0 += __shfl_xor_sync(0xffffffffu, s0, 2);
        s1 += __shfl_xor_sync(0xffffffffu, s1, 1);
        s1 += __shfl_xor_sync(0xffffffffu, s1, 2);
        l0 = l0 * f0 + s0;
        l1 = l1 * f1 + s1;

        if (__any_sync(0xffffffffu, upd)) {
            #pragma unroll
            for (int nt = 0; nt < 32; nt++) {
                o[nt][0] *= f0; o[nt][1] *= f0;
                o[nt][2] *= f1; o[nt][3] *= f1;
            }
        }

        // ---- PV: O[16 x 256] += P[16 x 64] * V[64 x 256]
        #pragma unroll
        for (int q = 0; q < 16; q++) {
            const uint32_t offV = (((2 * q + vS) ^ vSw) << 4);
            #pragma unroll
            for (int kk = 0; kk < 4; kk++) {
                uint32_t v0, v1, v2, v3;
                ldsm4t(v0, v1, v2, v3, vrb + kk * 8192 + offV);
                mma16816(o[2 * q + 0], pa[kk][0], pa[kk][1], pa[kk][2], pa[kk][3], v0, v1);
                mma16816(o[2 * q + 1], pa[kk][0], pa[kk][1], pa[kk][2], pa[kk][3], v2, v3);
            }
        }

        __syncthreads();      // all warps done reading sV
        if (it + 1 < NTOK / BN) {
            load_tile64_sw(sV, Vv + (size_t)(it + 1) * BN * CCH, t);
            CP_COMMIT();
            CP_WAIT(1);       // K(it+1) complete; V(it+1) may stay in flight
        }
        __syncthreads();
    }

    // ---- epilogue: O /= l, store hi/lo fp16 pair
    const float inv0 = 1.0f / l0, inv1 = 1.0f / l1;
    const int row0 = n0 + wr0 + (lane >> 2);
    const size_t base = ((size_t)b * NTOK + row0) * CCH + ((lane & 3) << 1);
    __half* __restrict__ Yh0 = g_y_hi + base;
    __half* __restrict__ Yl0 = g_y_lo + base;
    #pragma unroll
    for (int nt = 0; nt < 32; nt++) {
        float v0 = o[nt][0] * inv0, v1 = o[nt][1] * inv0;
        float v2 = o[nt][2] * inv1, v3 = o[nt][3] * inv1;
        __half h0 = __float2half(v0), h1 = __float2half(v1);
        __half h2 = __float2half(v2), h3 = __float2half(v3);
        *(__half2*)(Yh0 + nt * 8)            = __halves2half2(h0, h1);
        *(__half2*)(Yh0 + nt * 8 + 8 * CCH)  = __halves2half2(h2, h3);
        *(__half2*)(Yl0 + nt * 8)            = __halves2half2(__float2half(v0 - __half2float(h0)),
                                                              __float2half(v1 - __half2float(h1)));
        *(__half2*)(Yl0 + nt * 8 + 8 * CCH)  = __halves2half2(__float2half(v2 - __half2float(h2)),
                                                              __float2half(v3 - __half2float(h3)));
    }
}

// =============================================================================
// out_tc: out[b,oc,n] = x[b,oc,n] + gamma * sum_c w_out[oc,c] * Y[b,n,c]
// =============================================================================
__global__ void __launch_bounds__(256) out_tc_kernel(const float* __restrict__ x,
                                                     const float* __restrict__ gamma,
                                                     float* __restrict__ out) {
    const int b  = blockIdx.z;
    const int n0 = blockIdx.x * 128;
    const int m0 = blockIdx.y * 128;

    __shared__ __align__(16) __half sAh[128 * PA_LD];
    __shared__ __align__(16) __half sAl[128 * PA_LD];
    __shared__ __align__(16) __half sBh[128 * PA_LD];
    __shared__ __align__(16) __half sBl[128 * PA_LD];

    const int t    = threadIdx.x;
    const int lane = t & 31;
    const int warp = t >> 5;
    const int wr   = warp & 3;
    const int wc   = warp >> 2;

    const __half* __restrict__ Ah = g_w_hi + 3 * CCH * CCH;
    const __half* __restrict__ Al = g_w_lo + 3 * CCH * CCH;
    const __half* __restrict__ Bh = g_y_hi + (size_t)b * NTOK * CCH;
    const __half* __restrict__ Bl = g_y_lo + (size_t)b * NTOK * CCH;

    float acc[2][8][4] = {};

    const int gi = lane >> 3, li = lane & 7;
    const uint32_t aOff = (uint32_t)((wr * 32 + (lane & 15)) * PA_LD + ((lane >> 4) << 3)) * 2;
    const uint32_t bOff = (uint32_t)((wc * 64 + ((gi >> 1) << 3) + li) * PA_LD
                                     + ((gi & 1) << 3)) * 2;
    const uint32_t sAh32 = smem_u32(sAh), sAl32 = smem_u32(sAl);
    const uint32_t sBh32 = smem_u32(sBh), sBl32 = smem_u32(sBl);

    for (int k0 = 0; k0 < CCH; k0 += 32) {
        __syncthreads();
        {
            const int r = t >> 1, hoff = (t & 1) * 16;
            cp16(smem_u32(sAh + r * PA_LD + hoff),     Ah + (m0 + r) * CCH + k0 + hoff);
            cp16(smem_u32(sAh + r * PA_LD + hoff + 8), Ah + (m0 + r) * CCH + k0 + hoff + 8);
            cp16(smem_u32(sAl + r * PA_LD + hoff),     Al + (m0 + r) * CCH + k0 + hoff);
            cp16(smem_u32(sAl + r * PA_LD + hoff + 8), Al + (m0 + r) * CCH + k0 + hoff + 8);
            cp16(smem_u32(sBh + r * PA_LD + hoff),     Bh + (size_t)(n0 + r) * CCH + k0 + hoff);
            cp16(smem_u32(sBh + r * PA_LD + hoff + 8), Bh + (size_t)(n0 + r) * CCH + k0 + hoff + 8);
            cp16(smem_u32(sBl + r * PA_LD + hoff),     Bl + (size_t)(n0 + r) * CCH + k0 + hoff);
            cp16(smem_u32(sBl + r * PA_LD + hoff + 8), Bl + (size_t)(n0 + r) * CCH + k0 + hoff + 8);
        }
        CP_COMMIT();
        CP_WAIT(0);
        __syncthreads();

        #pragma unroll
        for (int ks = 0; ks < 2; ks++) {
            const uint32_t ka = ks * 32;
            uint32_t ah[2][4], al[2][4];
            ldsm4(ah[0][0], ah[0][1], ah[0][2], ah[0][3], sAh32 + aOff + ka);
            ldsm4(ah[1][0], ah[1][1], ah[1][2], ah[1][3], sAh32 + aOff + ka + 16 * PA_LD * 2);
            ldsm4(al[0][0], al[0][1], al[0][2], al[0][3], sAl32 + aOff + ka);
            ldsm4(al[1][0], al[1][1], al[1][2], al[1][3], sAl32 + aOff + ka + 16 * PA_LD * 2);
            #pragma unroll
            for (int jn = 0; jn < 4; jn++) {
                uint32_t bhf[4], blf[4];
                ldsm4(bhf[0], bhf[1], bhf[2], bhf[3], sBh32 + bOff + ka + jn * 16 * PA_LD * 2);
                ldsm4(blf[0], blf[1], blf[2], blf[3], sBl32 + bOff + ka + jn * 16 * PA_LD * 2);
                #pragma unroll
                for (int mi = 0; mi < 2; mi++) {
                    mma16816(acc[mi][2 * jn + 0], ah[mi][0], ah[mi][1], ah[mi][2], ah[mi][3], bhf[0], bhf[1]);
                    mma16816(acc[mi][2 * jn + 1], ah[mi][0], ah[mi][1], ah[mi][2], ah[mi][3], bhf[2], bhf[3]);
                    mma16816(acc[mi][2 * jn + 0], ah[mi][0], ah[mi][1], ah[mi][2], ah[mi][3], blf[0], blf[1]);
                    mma16816(acc[mi][2 * jn + 1], ah[mi][0], ah[mi][1], ah[mi][2], ah[mi][3], blf[2], blf[3]);
                    mma16816(acc[mi][2 * jn + 0], al[mi][0], al[mi][1], al[mi][2], al[mi][3], bhf[0], bhf[1]);
                    mma16816(acc[mi][2 * jn + 1], al[mi][0], al[mi][1], al[mi][2], al[mi][3], bhf[2], bhf[3]);
                }
            }
        }
    }

    const float gm = *gamma;
    const int mb = m0 + wr * 32 + (lane >> 2);
    const int nb = n0 + wc * 64 + (lane & 3) * 2;
    #pragma unroll
    for (int mi = 0; mi < 2; mi++)
        #pragma unroll
        for (int jn = 0; jn < 8; jn++) {
            const int m = mb + mi * 16;
            const int n = nb + jn * 8;
            {
                const size_t idx = ((size_t)b * CCH + m) * NTOK + n;
                float2 xv = *(const float2*)&x[idx];
                float2 r = {xv.x + gm * acc[mi][jn][0], xv.y + gm * acc[mi][jn][1]};
                *(float2*)&out[idx] = r;
            }
            {
                const size_t idx = ((size_t)b * CCH + m + 8) * NTOK + n;
                float2 xv = *(const float2*)&x[idx];
                float2 r = {xv.x + gm * acc[mi][jn][2], xv.y + gm * acc[mi][jn][3]};
                *(float2*)&out[idx] = r;
            }
        }
}

// =============================================================================
extern "C" void kernel_launch(void* const* d_in, const int* in_sizes, int n_in,
                              void* d_out, int out_size) {
    (void)in_sizes; (void)n_in; (void)out_size;
    const float* x      = (const float*)d_in[0];
    const float* w_th   = (const float*)d_in[1];
    const float* w_ph   = (const float*)d_in[2];
    const float* w_g    = (const float*)d_in[3];
    const float* w_out  = (const float*)d_in[4];
    const float* gamma  = (const float*)d_in[5];
    float* out = (float*)d_out;

    const int smem_bytes = 229376;   // Qh+Ql (128x512B each) + Kh+Kl+V (64x512B each)
    cudaFuncSetAttribute(flash_kernel, cudaFuncAttributeMaxDynamicSharedMemorySize,
                         smem_bytes);

    split_x_kernel<<<(BSZ * CCH * NTOK) / 1024, 256>>>(x);
    split_w_kernel<<<dim3(64, 4), 256>>>(w_th, w_ph, w_g, w_out);
    proj_tc_kernel<<<dim3(NTOK / 128, CCH / 128, BSZ * 3), 256>>>();
    flash_kernel  <<<dim3(NTOK / BM, BSZ), 256, smem_bytes>>>();
    out_tc_kernel <<<dim3(NTOK / 128, CCH / 128, BSZ), 256>>>(x, gamma, out);
}